// round 6
// baseline (speedup 1.0000x reference)
#include <cuda_runtime.h>

#define K2   49
#define KP   56      // padded token dim
#define NH   3
#define DIMC 96
#define NT   512

// ---- global scratch (precomputed by prep_kernel each invocation) ----
__device__ float gGwT[DIMC * DIMC];          // gGwT[he][c] = Gw[c*96+he]
__device__ float gBias[NH * K2 * K2];        // gBias[h][i*49+j] = rpb[rp[ij]*3+h]

// ---- shared memory layout (floats) ----
#define XT_STR  60
#define XT_OFF  0                               // xT[96][60]  xT[c][j]
#define P_OFF   (XT_OFF + 96 * XT_STR)          // 5760
#define P_STR   60                              // P[288][60]: Q rows 0..95, K 96..191, Y^T 192..287
#define S_OFF   (P_OFF + 288 * P_STR)           // 23040
#define S_STR   60                              // S[147][60]
#define VT_OFF  (S_OFF + 147 * S_STR)           // 31860
#define VT_STR  60                              // VT[96][60]  VT[he][i]
#define BOTT_OFF (VT_OFF + 96 * VT_STR)         // 37620
#define SMEM_FLOATS (BOTT_OFF + 64)             // 37684 floats = 150736 B

__device__ __forceinline__ float dot4(float4 a, float4 b, float acc) {
    acc = fmaf(a.x, b.x, acc);
    acc = fmaf(a.y, b.y, acc);
    acc = fmaf(a.z, b.z, acc);
    acc = fmaf(a.w, b.w, acc);
    return acc;
}
__device__ __forceinline__ float fcomp(float4 v, int k) {
    return k == 0 ? v.x : (k == 1 ? v.y : (k == 2 ? v.z : v.w));
}

// packed 2xfp32 fma: d = a*b + c (Blackwell FFMA2; same rounding as scalar fmaf)
__device__ __forceinline__ float2 ffma2(float2 a, float2 b, float2 c) {
    float2 d;
    asm("{\n\t"
        ".reg .b64 ra, rb, rc, rd;\n\t"
        "mov.b64 ra, {%2,%3};\n\t"
        "mov.b64 rb, {%4,%5};\n\t"
        "mov.b64 rc, {%6,%7};\n\t"
        "fma.rn.f32x2 rd, ra, rb, rc;\n\t"
        "mov.b64 {%0,%1}, rd;\n\t"
        "}"
        : "=f"(d.x), "=f"(d.y)
        : "f"(a.x), "f"(a.y), "f"(b.x), "f"(b.y), "f"(c.x), "f"(c.y));
    return d;
}

// ---- prep: transpose Gw, gather rpb via rp (once per invocation, not per CTA) ----
__global__ void prep_kernel(const float* __restrict__ Gw,
                            const float* __restrict__ rpb,
                            const int*   __restrict__ rp)
{
    int t = blockIdx.x * blockDim.x + threadIdx.x;
    if (t < DIMC * DIMC) {
        int c = t / DIMC, he = t - c * DIMC;
        gGwT[he * DIMC + c] = Gw[t];
    }
    if (t < NH * K2 * K2) {
        int h = t / (K2 * K2), ij = t - h * (K2 * K2);
        gBias[t] = rpb[rp[ij] * NH + h];
    }
}

__global__ __launch_bounds__(NT, 1)
void gwa_kernel(const float* __restrict__ x,    const float* __restrict__ mask,
                const float* __restrict__ qk_w, const float* __restrict__ qk_b,
                const float* __restrict__ botw, const float* __restrict__ botb,
                const float* __restrict__ Bw,   const float* __restrict__ pw,
                const float* __restrict__ pb,
                float* __restrict__ out, int nW)
{
    extern __shared__ float sm[];
    float* xT   = sm + XT_OFF;    // [96][60]  xT[c][j], cols 49..55 zero
    float* P    = sm + P_OFF;     // [288][60]
    float* S    = sm + S_OFF;     // [147][60]
    float* VT   = sm + VT_OFF;    // [96][60]
    float* bott = sm + BOTT_OFF;  // [56]

    const int b   = blockIdx.x;
    const int tid = threadIdx.x;
    const float* xg = x + (size_t)b * (K2 * DIMC);

    // ---------------- Phase 1: stage xT (transposed), bott ----------------
    for (int i = tid; i < K2 * DIMC; i += NT) {
        int j = i / DIMC, c = i - j * DIMC;
        xT[c * XT_STR + j] = xg[i];
    }
    for (int i = tid; i < DIMC * (KP - K2); i += NT) {   // zero xT cols 49..55
        int c = i / (KP - K2), j = K2 + (i % (KP - K2));
        xT[c * XT_STR + j] = 0.f;
    }
    if (tid < KP) {
        float acc = 0.f;
        if (tid < K2) {
            const float4* xr  = (const float4*)(xg + tid * DIMC);
            const float4* bw4 = (const float4*)botw;
            acc = botb[0];
            #pragma unroll 6
            for (int c4 = 0; c4 < 24; c4++) acc = dot4(xr[c4], bw4[c4], acc);
        }
        bott[tid] = acc;
    }
    __syncthreads();

    // ---------------- Phase 2: fused Q/K/Y projection, 8r x 4j tiles (504) ----------------
    const float SCALE = 0.17677669529663687f;  // 32^-0.5
    if (tid < 504) {
        const int rt = tid / 14;
        const int jt = tid - rt * 14;
        const int r0 = rt * 8;
        const int j0 = jt * 4;
        const bool isQK = (r0 < 192);
        const float* wbase = isQK ? (qk_w + r0 * 96) : (gGwT + (r0 - 192) * 96);

        float2 acc[8][2];   // pairs along j
        #pragma unroll
        for (int a = 0; a < 8; a++) {
            float bv = isQK ? qk_b[r0 + a] : 0.f;
            acc[a][0] = make_float2(bv, bv);
            acc[a][1] = make_float2(bv, bv);
        }

        #pragma unroll 2
        for (int c0 = 0; c0 < DIMC; c0 += 4) {
            float2 xlo[4], xhi[4];
            #pragma unroll
            for (int cc = 0; cc < 4; cc++) {
                float4 xv = *(const float4*)&xT[(c0 + cc) * XT_STR + j0];
                xlo[cc] = make_float2(xv.x, xv.y);
                xhi[cc] = make_float2(xv.z, xv.w);
            }
            #pragma unroll
            for (int a = 0; a < 8; a++) {
                float4 wv = *(const float4*)&wbase[a * 96 + c0];
                #pragma unroll
                for (int cc = 0; cc < 4; cc++) {
                    float w = fcomp(wv, cc);
                    float2 w2 = make_float2(w, w);
                    acc[a][0] = ffma2(w2, xlo[cc], acc[a][0]);
                    acc[a][1] = ffma2(w2, xhi[cc], acc[a][1]);
                }
            }
        }

        const float s = (r0 < 96) ? SCALE : 1.f;
        #pragma unroll
        for (int a = 0; a < 8; a++) {
            float4 o = make_float4(acc[a][0].x * s, acc[a][0].y * s,
                                   acc[a][1].x * s, acc[a][1].y * s);
            *(float4*)&P[(r0 + a) * P_STR + j0] = o;
        }
    }
    __syncthreads();

    // ---------------- Phase 3: logits 4i x 4j tiles (507) + bias/mask ----------------
    const float* maskb = mask + (size_t)(b % nW) * (K2 * K2);
    if (tid < 507) {
        const int h   = tid / 169;
        const int rem = tid - h * 169;
        const int it  = rem / 13;
        const int jt  = rem - it * 13;
        const int i0  = it * 4;
        const int j0  = jt * 4;
        const float* qbase = P + (h * 32) * P_STR + i0;
        const float* kbase = P + (96 + h * 32) * P_STR + j0;

        float2 acc[4][2];
        #pragma unroll
        for (int ii = 0; ii < 4; ii++) {
            acc[ii][0] = make_float2(0.f, 0.f);
            acc[ii][1] = make_float2(0.f, 0.f);
        }

        #pragma unroll 4
        for (int e = 0; e < 32; e++) {
            float4 qv = *(const float4*)&qbase[e * P_STR];
            float4 kv = *(const float4*)&kbase[e * P_STR];
            float2 kp0 = make_float2(kv.x, kv.y);
            float2 kp1 = make_float2(kv.z, kv.w);
            #pragma unroll
            for (int ii = 0; ii < 4; ii++) {
                float q = fcomp(qv, ii);
                float2 q2 = make_float2(q, q);
                acc[ii][0] = ffma2(q2, kp0, acc[ii][0]);
                acc[ii][1] = ffma2(q2, kp1, acc[ii][1]);
            }
        }

        const float* biash = gBias + h * (K2 * K2);
        #pragma unroll
        for (int ii = 0; ii < 4; ii++) {
            int i = i0 + ii;
            if (i < K2) {
                float* srow = S + (h * K2 + i) * S_STR;
                float av[4] = { acc[ii][0].x, acc[ii][0].y, acc[ii][1].x, acc[ii][1].y };
                #pragma unroll
                for (int jj = 0; jj < 4; jj++) {
                    int j = j0 + jj;
                    float v = av[jj];
                    if (j < K2) {
                        int idx = i * K2 + j;
                        v += biash[idx] + maskb[idx];
                    }
                    srow[j] = v;
                }
            }
        }
    }
    __syncthreads();

    // ---------------- Phase 4: softmax, warp per row ----------------
    {
        int warp = tid >> 5, lane = tid & 31;
        for (int row = warp; row < NH * K2; row += NT / 32) {
            float* srow = S + row * S_STR;
            float v0 = srow[lane];
            float v1 = (lane < 17) ? srow[32 + lane] : -1e30f;
            float m = fmaxf(v0, v1);
            #pragma unroll
            for (int o = 16; o; o >>= 1) m = fmaxf(m, __shfl_xor_sync(~0u, m, o));
            float e0 = __expf(v0 - m);
            float e1 = (lane < 17) ? __expf(v1 - m) : 0.f;
            float sum = e0 + e1;
            #pragma unroll
            for (int o = 16; o; o >>= 1) sum += __shfl_xor_sync(~0u, sum, o);
            float inv = __fdividef(1.f, sum);
            srow[lane] = e0 * inv;
            if (lane < 17) srow[32 + lane] = e1 * inv;
        }
    }
    __syncthreads();

    // ---------------- Phase 5: VT[he][i] = bott[i]*(S@Y^T + Bw), 4i x 4e tiles (312) ----------------
    if (tid < 312) {
        const int h   = tid / 104;
        const int rem = tid - h * 104;
        const int et  = rem / 13;
        const int it  = rem - et * 13;
        const int i0  = it * 4;
        const int e0  = et * 4;
        const float* sbase = S + (h * K2 + i0) * S_STR;
        const float* ybase = P + (192 + h * 32 + e0) * P_STR;

        float2 acc[4][4];
        #pragma unroll
        for (int ii = 0; ii < 4; ii++)
            #pragma unroll
            for (int ee = 0; ee < 4; ee++) acc[ii][ee] = make_float2(0.f, 0.f);

        #pragma unroll 2
        for (int j0 = 0; j0 < KP; j0 += 4) {
            float2 sp[4][2], yp[4][2];
            #pragma unroll
            for (int ii = 0; ii < 4; ii++) {
                float4 sv = *(const float4*)&sbase[ii * S_STR + j0];
                sp[ii][0] = make_float2(sv.x, sv.y);
                sp[ii][1] = make_float2(sv.z, sv.w);
            }
            #pragma unroll
            for (int ee = 0; ee < 4; ee++) {
                float4 yv = *(const float4*)&ybase[ee * P_STR + j0];
                yp[ee][0] = make_float2(yv.x, yv.y);
                yp[ee][1] = make_float2(yv.z, yv.w);
            }
            #pragma unroll
            for (int ii = 0; ii < 4; ii++)
                #pragma unroll
                for (int ee = 0; ee < 4; ee++) {
                    acc[ii][ee] = ffma2(sp[ii][0], yp[ee][0], acc[ii][ee]);
                    acc[ii][ee] = ffma2(sp[ii][1], yp[ee][1], acc[ii][ee]);
                }
        }

        float bt[4];
        #pragma unroll
        for (int ii = 0; ii < 4; ii++) bt[ii] = bott[i0 + ii];
        #pragma unroll
        for (int ee = 0; ee < 4; ee++) {
            float bw = Bw[h * 32 + e0 + ee];
            float4 o = make_float4(bt[0] * (acc[0][ee].x + acc[0][ee].y + bw),
                                   bt[1] * (acc[1][ee].x + acc[1][ee].y + bw),
                                   bt[2] * (acc[2][ee].x + acc[2][ee].y + bw),
                                   bt[3] * (acc[3][ee].x + acc[3][ee].y + bw));
            *(float4*)&VT[(h * 32 + e0 + ee) * VT_STR + i0] = o;
        }
    }
    __syncthreads();

    // ---------------- Phase 6: out[i][d] = sum_he VT[he][i]*pw[d][he], 4d x 4i tiles (312) ----------------
    float* og = out + (size_t)b * (K2 * DIMC);
    if (tid < 312) {
        const int dt = tid / 13;
        const int it = tid - dt * 13;
        const int d0 = dt * 4;
        const int i0 = it * 4;

        float2 acc[2][4];   // 2 i-pairs x 4 d
        #pragma unroll
        for (int dd = 0; dd < 4; dd++) {
            float bv = pb[d0 + dd];
            acc[0][dd] = make_float2(bv, bv);
            acc[1][dd] = make_float2(bv, bv);
        }

        #pragma unroll 2
        for (int c0 = 0; c0 < DIMC; c0 += 4) {
            float2 vlo[4], vhi[4];
            #pragma unroll
            for (int cc = 0; cc < 4; cc++) {
                float4 vv = *(const float4*)&VT[(c0 + cc) * VT_STR + i0];
                vlo[cc] = make_float2(vv.x, vv.y);
                vhi[cc] = make_float2(vv.z, vv.w);
            }
            #pragma unroll
            for (int dd = 0; dd < 4; dd++) {
                float4 wv = *(const float4*)&pw[(d0 + dd) * 96 + c0];
                #pragma unroll
                for (int cc = 0; cc < 4; cc++) {
                    float w = fcomp(wv, cc);
                    float2 w2 = make_float2(w, w);
                    acc[0][dd] = ffma2(w2, vlo[cc], acc[0][dd]);
                    acc[1][dd] = ffma2(w2, vhi[cc], acc[1][dd]);
                }
            }
        }

        #pragma unroll
        for (int ip = 0; ip < 2; ip++) {
            #pragma unroll
            for (int half = 0; half < 2; half++) {
                int i = i0 + ip * 2 + half;
                if (i < K2) {
                    float4 o = (half == 0)
                        ? make_float4(acc[ip][0].x, acc[ip][1].x, acc[ip][2].x, acc[ip][3].x)
                        : make_float4(acc[ip][0].y, acc[ip][1].y, acc[ip][2].y, acc[ip][3].y);
                    *(float4*)&og[i * DIMC + d0] = o;
                }
            }
        }
    }
}

extern "C" void kernel_launch(void* const* d_in, const int* in_sizes, int n_in,
                              void* d_out, int out_size) {
    const float* x    = (const float*)d_in[0];
    const float* mask = (const float*)d_in[1];
    const float* qk_w = (const float*)d_in[2];
    const float* qk_b = (const float*)d_in[3];
    const float* rpb  = (const float*)d_in[4];
    const float* botw = (const float*)d_in[5];
    const float* botb = (const float*)d_in[6];
    const float* Gw   = (const float*)d_in[7];
    const float* Bw   = (const float*)d_in[8];
    const float* pw   = (const float*)d_in[9];
    const float* pb   = (const float*)d_in[10];
    const int*   rp   = (const int*)d_in[11];

    const int BW = in_sizes[0] / (K2 * DIMC);        // 128
    const int nW = in_sizes[1] / (K2 * K2);          // 64

    prep_kernel<<<(DIMC * DIMC + 255) / 256, 256>>>(Gw, rpb, rp);

    size_t smem = SMEM_FLOATS * sizeof(float);
    cudaFuncSetAttribute(gwa_kernel, cudaFuncAttributeMaxDynamicSharedMemorySize, (int)smem);
    gwa_kernel<<<BW, NT, smem>>>(x, mask, qk_w, qk_b, botw, botb,
                                 Bw, pw, pb, (float*)d_out, nW);
}